// round 13
// baseline (speedup 1.0000x reference)
#include <cuda_runtime.h>
#include <cuda_fp16.h>
#include <cstdint>

// Scratch (no cudaMalloc allowed)
__device__ __half g_qkv[50331648];    // 8192 x 6144 fp16
__device__ __half g_hx [16777216];    // x     fp16
__device__ __half g_hw1[12582912];    // w_qkv fp16
__device__ __half g_hw2[ 4194304];    // w_out fp16
__device__ __half g_att[16777216];    // attention output (permuted) fp16

#define BK 64                 // k halves per stage (128B rows)
#define NSTG 3
#define STG_BYTES 32768       // A 16KB + B 16KB

__device__ __forceinline__ uint32_t smem_u32(const void* p) {
    uint32_t a;
    asm("{ .reg .u64 t; cvta.to.shared.u64 t, %1; cvt.u32.u64 %0, t; }" : "=r"(a) : "l"(p));
    return a;
}
__device__ __forceinline__ void cp16(uint32_t s, const void* g) {
    asm volatile("cp.async.cg.shared.global [%0], [%1], 16;" :: "r"(s), "l"(g));
}
__device__ __forceinline__ void cp_commit() {
    asm volatile("cp.async.commit_group;" ::: "memory");
}
__device__ __forceinline__ void cp_wait(int n) {
    if (n == 0) asm volatile("cp.async.wait_group 0;" ::: "memory");
    else        asm volatile("cp.async.wait_group 1;" ::: "memory");
}
__device__ __forceinline__ void ldm4(uint32_t* r, uint32_t addr) {
    asm volatile("ldmatrix.sync.aligned.m8n8.x4.shared.b16 {%0,%1,%2,%3}, [%4];"
                 : "=r"(r[0]), "=r"(r[1]), "=r"(r[2]), "=r"(r[3]) : "r"(addr));
}
__device__ __forceinline__ void ldm4t(uint32_t* r, uint32_t addr) {
    asm volatile("ldmatrix.sync.aligned.m8n8.x4.trans.shared.b16 {%0,%1,%2,%3}, [%4];"
                 : "=r"(r[0]), "=r"(r[1]), "=r"(r[2]), "=r"(r[3]) : "r"(addr));
}
__device__ __forceinline__ void mma_fp16(float* c, const uint32_t* a, const uint32_t* b) {
    asm volatile(
        "mma.sync.aligned.m16n8k16.row.col.f32.f16.f16.f32 "
        "{%0,%1,%2,%3}, {%4,%5,%6,%7}, {%8,%9}, {%0,%1,%2,%3};"
        : "+f"(c[0]), "+f"(c[1]), "+f"(c[2]), "+f"(c[3])
        : "r"(a[0]), "r"(a[1]), "r"(a[2]), "r"(a[3]), "r"(b[0]), "r"(b[1]));
}

// fp32 -> fp16 conversion over x, w_qkv, w_out in ONE launch.
// Layout: [x: 16777216][w_qkv: 12582912][w_out: 4194304] floats = 8388608 float4.
__global__ __launch_bounds__(256, 1) void f2h_all(
    const float4* __restrict__ x, const float4* __restrict__ w1,
    const float4* __restrict__ w2,
    uint2* __restrict__ ox, uint2* __restrict__ ow1, uint2* __restrict__ ow2)
{
    int i = blockIdx.x * 512 + threadIdx.x;
    #pragma unroll
    for (int u = 0; u < 2; ++u, i += 256) {
        const float4* in;
        uint2* out;
        int j = i;
        if (j < 4194304) { in = x; out = ox; }
        else if (j < 4194304 + 3145728) { in = w1; out = ow1; j -= 4194304; }
        else { in = w2; out = ow2; j -= (4194304 + 3145728); }
        float4 v = in[j];
        __half2 lo = __floats2half2_rn(v.x, v.y);
        __half2 hi = __floats2half2_rn(v.z, v.w);
        uint2 o;
        o.x = *(uint32_t*)&lo;
        o.y = *(uint32_t*)&hi;
        out[j] = o;
    }
}

// ---------------- GEMM: 128 thr, 64x64 warp tiles, 2 CTA/SM ----------------
// Full-stage loader (prologue only)
__device__ __forceinline__ void load_stage(uint32_t sbase, const __half* __restrict__ A,
                                           const __half* __restrict__ W, int mb, int nb,
                                           int K, int kt, int tid) {
    const uint32_t aB = sbase, bB = sbase + 16384;
    const __half* Ap = A + (size_t)mb * K + kt * BK;
    const __half* Wp = W + (size_t)nb * K + kt * BK;
    #pragma unroll
    for (int i = 0; i < 8; ++i) {
        int id = tid + i * 128;
        int r  = id >> 3;
        int c  = id & 7;
        uint32_t d = ((uint32_t)(r << 3) + (uint32_t)(c ^ (r & 7))) << 4;
        cp16(aB + d, Ap + (size_t)r * K + c * 8);
        cp16(bB + d, Wp + (size_t)r * K + c * 8);
    }
    cp_commit();
}

// Quarter-stage loader: 2 of the 8 iterations; spreads LSU pressure across ks.
__device__ __forceinline__ void load_quarter(uint32_t sbase, const __half* __restrict__ A,
                                             const __half* __restrict__ W, int mb, int nb,
                                             int K, int kt, int tid, int q) {
    const uint32_t aB = sbase, bB = sbase + 16384;
    const __half* Ap = A + (size_t)mb * K + kt * BK;
    const __half* Wp = W + (size_t)nb * K + kt * BK;
    #pragma unroll
    for (int i = 2 * q; i < 2 * q + 2; ++i) {
        int id = tid + i * 128;
        int r  = id >> 3;
        int c  = id & 7;
        uint32_t d = ((uint32_t)(r << 3) + (uint32_t)(c ^ (r & 7))) << 4;
        cp16(aB + d, Ap + (size_t)r * K + c * 8);
        cp16(bB + d, Wp + (size_t)r * K + c * 8);
    }
}

template <bool HALF_OUT>
__global__ __launch_bounds__(128, 2) void gemm_fp16(
    const __half* __restrict__ A, const __half* __restrict__ W,
    const float* __restrict__ bias, void* __restrict__ Cv,
    int M, int N, int K)
{
    extern __shared__ char smem[];
    const uint32_t sb = smem_u32(smem);

    const int tid   = threadIdx.x;
    const int warp  = tid >> 5;
    const int lane  = tid & 31;
    const int wm    = (warp >> 1) << 6;
    const int wn    = (warp & 1) << 6;
    const int lane7 = lane & 7;
    const int sel   = lane >> 3;
    const int grp   = lane >> 2;
    const int qt    = lane & 3;

    const int mb = blockIdx.y * 128;
    const int nb = blockIdx.x * 128;
    const int NT = K / BK;

    float acc[4][8][4];
    #pragma unroll
    for (int i = 0; i < 4; ++i)
        #pragma unroll
        for (int j = 0; j < 8; ++j)
            #pragma unroll
            for (int q = 0; q < 4; ++q)
                acc[i][j][q] = 0.f;

    load_stage(sb + 0 * STG_BYTES, A, W, mb, nb, K, 0, tid);
    load_stage(sb + 1 * STG_BYTES, A, W, mb, nb, K, 1, tid);

    uint32_t rA[4], rAx[4], rB[4], rBx[4];
    #pragma unroll
    for (int i = 0; i < 4; ++i) {
        uint32_t r = (uint32_t)(wm + i * 16 + ((sel & 1) << 3) + lane7);
        rA[i]  = r << 7;
        rAx[i] = r & 7;
    }
    #pragma unroll
    for (int j = 0; j < 4; ++j) {
        uint32_t r = (uint32_t)(wn + j * 16 + ((sel >> 1) << 3) + lane7);
        rB[j]  = r << 7;
        rBx[j] = r & 7;
    }
    const uint32_t cA0 = (uint32_t)(sel >> 1);
    const uint32_t cB0 = (uint32_t)(sel & 1);

    for (int kt = 0; kt < NT; ++kt) {
        cp_wait(kt < NT - 1 ? 1 : 0);
        __syncthreads();

        const uint32_t aS = sb + (uint32_t)(kt % NSTG) * STG_BYTES;
        const uint32_t bS = aS + 16384;
        const bool pf = (kt + 2 < NT);
        const uint32_t pS = sb + (uint32_t)((kt + 2) % NSTG) * STG_BYTES;

        #pragma unroll
        for (int ks = 0; ks < 4; ++ks) {
            uint32_t af[4][4], bf[8][2];
            #pragma unroll
            for (int i = 0; i < 4; ++i) {
                uint32_t c = (uint32_t)(2 * ks) + cA0;
                ldm4(af[i], aS + rA[i] + ((c ^ rAx[i]) << 4));
            }
            #pragma unroll
            for (int j = 0; j < 4; ++j) {
                uint32_t c = (uint32_t)(2 * ks) + cB0;
                uint32_t r4[4];
                ldm4(r4, bS + rB[j] + ((c ^ rBx[j]) << 4));
                bf[2 * j][0]     = r4[0];
                bf[2 * j][1]     = r4[1];
                bf[2 * j + 1][0] = r4[2];
                bf[2 * j + 1][1] = r4[3];
            }

            // Spread prefetch: quarter of stage kt+2 per ks, commit at ks=3.
            if (pf) {
                load_quarter(pS, A, W, mb, nb, K, kt + 2, tid, ks);
                if (ks == 3) cp_commit();
            }

            #pragma unroll
            for (int i = 0; i < 4; ++i)
                #pragma unroll
                for (int j = 0; j < 8; ++j)
                    mma_fp16(acc[i][j], af[i], bf[j]);
        }
    }

    #pragma unroll
    for (int i = 0; i < 4; ++i) {
        const int r0 = mb + wm + i * 16 + grp;
        #pragma unroll
        for (int j = 0; j < 8; ++j) {
            const int cc = nb + wn + j * 8 + (qt << 1);
            float2 bb = *(const float2*)(bias + cc);
            float v00 = acc[i][j][0] + bb.x, v01 = acc[i][j][1] + bb.y;
            float v10 = acc[i][j][2] + bb.x, v11 = acc[i][j][3] + bb.y;
            if (HALF_OUT) {
                __half* C = (__half*)Cv;
                __half2 h0 = __floats2half2_rn(v00, v01);
                __half2 h1 = __floats2half2_rn(v10, v11);
                *(uint32_t*)(C + (size_t)r0 * N + cc)       = *(uint32_t*)&h0;
                *(uint32_t*)(C + (size_t)(r0 + 8) * N + cc) = *(uint32_t*)&h1;
            } else {
                float* C = (float*)Cv;
                float2 v0{v00, v01}, v1{v10, v11};
                *(float2*)(C + (size_t)r0 * N + cc)       = v0;
                *(float2*)(C + (size_t)(r0 + 8) * N + cc) = v1;
            }
        }
    }
}

// ---------------- MMA attention: 1 warp per token, 4 tokens per block ----------------
__global__ __launch_bounds__(128, 4) void attn_mma(
    const __half* __restrict__ qkv, __half* __restrict__ out)
{
    __shared__ __align__(16) char sm[4 * 12288];
    const uint32_t sb = smem_u32(sm);
    const int tid  = threadIdx.x;
    const int w    = tid >> 5;
    const int lane = tid & 31;
    const int t0   = blockIdx.x * 4;

    #pragma unroll
    for (int i = 0; i < 24; ++i) {
        int j = tid + i * 128;
        int s = j / 768;
        int r = j - s * 768;
        int which = r >> 8;
        int hr    = (r >> 4) & 15;
        int c     = r & 15;
        uint32_t d = (uint32_t)s * 12288 + (uint32_t)which * 4096
                   + (uint32_t)hr * 256 + ((uint32_t)(c ^ (hr & 7)) << 4);
        cp16(sb + d, qkv + ((size_t)(t0 + s) * 6144 + which * 2048 + hr * 128 + c * 8));
    }
    cp_commit();
    cp_wait(0);
    __syncthreads();

    const uint32_t qb = sb + (uint32_t)w * 12288;
    const uint32_t kb = qb + 4096;
    const uint32_t vb = qb + 8192;

    const int lane7 = lane & 7;
    const int sel   = lane >> 3;
    const int grp   = lane >> 2;
    const int qt    = lane & 3;

    const uint32_t rowA  = ((uint32_t)(sel & 1) << 3) + lane7;
    const uint32_t aRow  = qb + rowA * 256;
    const uint32_t rAx   = rowA & 7;
    const uint32_t rowB  = ((uint32_t)(sel >> 1) << 3) + lane7;
    const uint32_t bRow  = kb + rowB * 256;
    const uint32_t rBx   = rowB & 7;
    const uint32_t vRowi = ((uint32_t)(sel & 1) << 3) + lane7;
    const uint32_t vRow  = vb + vRowi * 256;
    const uint32_t rVx   = vRowi & 7;

    float s0[4] = {0.f, 0.f, 0.f, 0.f};
    float s1[4] = {0.f, 0.f, 0.f, 0.f};
    #pragma unroll
    for (int kk = 0; kk < 8; ++kk) {
        uint32_t a[4], k4[4];
        uint32_t cA = (uint32_t)(kk * 2) + (uint32_t)(sel >> 1);
        ldm4(a, aRow + ((cA ^ rAx) << 4));
        uint32_t cB = (uint32_t)(kk * 2) + (uint32_t)(sel & 1);
        ldm4(k4, bRow + ((cB ^ rBx) << 4));
        mma_fp16(s0, a, k4);
        mma_fp16(s1, a, k4 + 2);
    }

    const float sc = 0.022097086912079608f;   // 1/sqrt(2048)
    float l0 = s0[0]*sc, l1 = s0[1]*sc, l2 = s1[0]*sc, l3 = s1[1]*sc;
    float h0 = s0[2]*sc, h1 = s0[3]*sc, h2 = s1[2]*sc, h3 = s1[3]*sc;

    float mlo = fmaxf(fmaxf(l0, l1), fmaxf(l2, l3));
    float mhi = fmaxf(fmaxf(h0, h1), fmaxf(h2, h3));
    #pragma unroll
    for (int o = 1; o <= 2; o <<= 1) {
        mlo = fmaxf(mlo, __shfl_xor_sync(0xFFFFFFFFu, mlo, o));
        mhi = fmaxf(mhi, __shfl_xor_sync(0xFFFFFFFFu, mhi, o));
    }
    float e0 = __expf(l0 - mlo), e1 = __expf(l1 - mlo), e2 = __expf(l2 - mlo), e3 = __expf(l3 - mlo);
    float f0 = __expf(h0 - mhi), f1 = __expf(h1 - mhi), f2 = __expf(h2 - mhi), f3 = __expf(h3 - mhi);
    float slo = e0 + e1 + e2 + e3;
    float shi = f0 + f1 + f2 + f3;
    #pragma unroll
    for (int o = 1; o <= 2; o <<= 1) {
        slo += __shfl_xor_sync(0xFFFFFFFFu, slo, o);
        shi += __shfl_xor_sync(0xFFFFFFFFu, shi, o);
    }
    const float ilo = 1.f / slo, ihi = 1.f / shi;

    uint32_t pa[4];
    {
        __half2 t;
        t = __floats2half2_rn(e0 * ilo, e1 * ilo); pa[0] = *(uint32_t*)&t;
        t = __floats2half2_rn(f0 * ihi, f1 * ihi); pa[1] = *(uint32_t*)&t;
        t = __floats2half2_rn(e2 * ilo, e3 * ilo); pa[2] = *(uint32_t*)&t;
        t = __floats2half2_rn(f2 * ihi, f3 * ihi); pa[3] = *(uint32_t*)&t;
    }

    float o[16][4];
    #pragma unroll
    for (int i = 0; i < 16; ++i)
        #pragma unroll
        for (int q = 0; q < 4; ++q)
            o[i][q] = 0.f;

    #pragma unroll
    for (int dt = 0; dt < 8; ++dt) {
        uint32_t cV = (uint32_t)(dt * 2) + (uint32_t)(sel >> 1);
        uint32_t v4[4];
        ldm4t(v4, vRow + ((cV ^ rVx) << 4));
        mma_fp16(o[2 * dt],     pa, v4);
        mma_fp16(o[2 * dt + 1], pa, v4 + 2);
    }

    const int t = t0 + w;
    const int b = t >> 11;
    const int n = t & 2047;
    const size_t blk = (size_t)b * 4194304u + (size_t)(n >> 4) * 2048 + (size_t)(n & 15) * 128;
    const size_t ob_lo = blk + (size_t)grp * (128u * 2048u);
    const size_t ob_hi = blk + (size_t)(grp + 8) * (128u * 2048u);
    #pragma unroll
    for (int dt = 0; dt < 16; ++dt) {
        const int d = dt * 8 + 2 * qt;
        __half2 vlo = __floats2half2_rn(o[dt][0], o[dt][1]);
        __half2 vhi = __floats2half2_rn(o[dt][2], o[dt][3]);
        *(uint32_t*)(out + ob_lo + d) = *(uint32_t*)&vlo;
        *(uint32_t*)(out + ob_hi + d) = *(uint32_t*)&vhi;
    }
}

extern "C" void kernel_launch(void* const* d_in, const int* in_sizes, int n_in,
                              void* d_out, int out_size)
{
    const float* x     = (const float*)d_in[0];
    const float* w_qkv = (const float*)d_in[1];
    const float* b_qkv = (const float*)d_in[2];
    const float* w_out = (const float*)d_in[3];
    const float* b_out = (const float*)d_in[4];
    float* out = (float*)d_out;

    __half *qkv, *hx, *hw1, *hw2, *att;
    cudaGetSymbolAddress((void**)&qkv, g_qkv);
    cudaGetSymbolAddress((void**)&hx,  g_hx);
    cudaGetSymbolAddress((void**)&hw1, g_hw1);
    cudaGetSymbolAddress((void**)&hw2, g_hw2);
    cudaGetSymbolAddress((void**)&att, g_att);

    // one conversion launch: 8388608 float4 total / 512 per block
    f2h_all<<<16384, 256>>>((const float4*)x, (const float4*)w_qkv, (const float4*)w_out,
                            (uint2*)hx, (uint2*)hw1, (uint2*)hw2);

    const int smem_bytes = NSTG * STG_BYTES;   // 96KB
    cudaFuncSetAttribute(gemm_fp16<true>,  cudaFuncAttributeMaxDynamicSharedMemorySize, smem_bytes);
    cudaFuncSetAttribute(gemm_fp16<false>, cudaFuncAttributeMaxDynamicSharedMemorySize, smem_bytes);

    // QKV projection -> fp16 qkv
    dim3 g1(6144 / 128, 8192 / 128);
    gemm_fp16<true><<<g1, 128, smem_bytes>>>(hx, hw1, b_qkv, qkv, 8192, 6144, 2048);

    // MMA attention + permutation (fp16 -> fp16), 4 tokens/block
    attn_mma<<<2048, 128>>>(qkv, att);

    // output projection -> fp32 out
    dim3 g2(2048 / 128, 8192 / 128);
    gemm_fp16<false><<<g2, 128, smem_bytes>>>(att, hw2, b_out, out, 8192, 2048, 2048);
}

// round 15
// speedup vs baseline: 1.0331x; 1.0331x over previous
#include <cuda_runtime.h>
#include <cuda_fp16.h>
#include <cstdint>

// Scratch (no cudaMalloc allowed)
__device__ __half g_qkv[50331648];    // 8192 x 6144 fp16
__device__ __half g_hx [16777216];    // x     fp16
__device__ __half g_hw1[12582912];    // w_qkv fp16
__device__ __half g_hw2[ 4194304];    // w_out fp16
__device__ __half g_att[16777216];    // attention output (permuted) fp16

#define BK 64                 // k halves per stage (128B rows)
#define NSTG 3
#define STG_BYTES 32768       // A 16KB + B 16KB

__device__ __forceinline__ uint32_t smem_u32(const void* p) {
    uint32_t a;
    asm("{ .reg .u64 t; cvta.to.shared.u64 t, %1; cvt.u32.u64 %0, t; }" : "=r"(a) : "l"(p));
    return a;
}
__device__ __forceinline__ void cp16(uint32_t s, const void* g) {
    asm volatile("cp.async.cg.shared.global [%0], [%1], 16;" :: "r"(s), "l"(g));
}
__device__ __forceinline__ void cp_commit() {
    asm volatile("cp.async.commit_group;" ::: "memory");
}
__device__ __forceinline__ void cp_wait(int n) {
    if (n == 0) asm volatile("cp.async.wait_group 0;" ::: "memory");
    else        asm volatile("cp.async.wait_group 1;" ::: "memory");
}
__device__ __forceinline__ void ldm4(uint32_t* r, uint32_t addr) {
    asm volatile("ldmatrix.sync.aligned.m8n8.x4.shared.b16 {%0,%1,%2,%3}, [%4];"
                 : "=r"(r[0]), "=r"(r[1]), "=r"(r[2]), "=r"(r[3]) : "r"(addr));
}
__device__ __forceinline__ void ldm4t(uint32_t* r, uint32_t addr) {
    asm volatile("ldmatrix.sync.aligned.m8n8.x4.trans.shared.b16 {%0,%1,%2,%3}, [%4];"
                 : "=r"(r[0]), "=r"(r[1]), "=r"(r[2]), "=r"(r[3]) : "r"(addr));
}
__device__ __forceinline__ void mma_fp16(float* c, const uint32_t* a, const uint32_t* b) {
    asm volatile(
        "mma.sync.aligned.m16n8k16.row.col.f32.f16.f16.f32 "
        "{%0,%1,%2,%3}, {%4,%5,%6,%7}, {%8,%9}, {%0,%1,%2,%3};"
        : "+f"(c[0]), "+f"(c[1]), "+f"(c[2]), "+f"(c[3])
        : "r"(a[0]), "r"(a[1]), "r"(a[2]), "r"(a[3]), "r"(b[0]), "r"(b[1]));
}

// fp32 -> fp16 conversion over x, w_qkv, w_out in ONE launch.
__global__ __launch_bounds__(256, 1) void f2h_all(
    const float4* __restrict__ x, const float4* __restrict__ w1,
    const float4* __restrict__ w2,
    uint2* __restrict__ ox, uint2* __restrict__ ow1, uint2* __restrict__ ow2)
{
    int i = blockIdx.x * 512 + threadIdx.x;
    #pragma unroll
    for (int u = 0; u < 2; ++u, i += 256) {
        const float4* in;
        uint2* out;
        int j = i;
        if (j < 4194304) { in = x; out = ox; }
        else if (j < 4194304 + 3145728) { in = w1; out = ow1; j -= 4194304; }
        else { in = w2; out = ow2; j -= (4194304 + 3145728); }
        float4 v = in[j];
        __half2 lo = __floats2half2_rn(v.x, v.y);
        __half2 hi = __floats2half2_rn(v.z, v.w);
        uint2 o;
        o.x = *(uint32_t*)&lo;
        o.y = *(uint32_t*)&hi;
        out[j] = o;
    }
}

// ---------------- GEMM: 128 thr, 64x64 warp tiles, 2 CTA/SM (R12 schedule) ----------------
__device__ __forceinline__ void load_stage(uint32_t sbase, const __half* __restrict__ A,
                                           const __half* __restrict__ W, int mb, int nb,
                                           int K, int kt, int tid) {
    const uint32_t aB = sbase, bB = sbase + 16384;
    const __half* Ap = A + (size_t)mb * K + kt * BK;
    const __half* Wp = W + (size_t)nb * K + kt * BK;
    #pragma unroll
    for (int i = 0; i < 8; ++i) {
        int id = tid + i * 128;
        int r  = id >> 3;
        int c  = id & 7;
        uint32_t d = ((uint32_t)(r << 3) + (uint32_t)(c ^ (r & 7))) << 4;
        cp16(aB + d, Ap + (size_t)r * K + c * 8);
        cp16(bB + d, Wp + (size_t)r * K + c * 8);
    }
    cp_commit();
}

template <bool HALF_OUT>
__global__ __launch_bounds__(128, 2) void gemm_fp16(
    const __half* __restrict__ A, const __half* __restrict__ W,
    const float* __restrict__ bias, void* __restrict__ Cv,
    int M, int N, int K)
{
    extern __shared__ char smem[];
    const uint32_t sb = smem_u32(smem);

    const int tid   = threadIdx.x;
    const int warp  = tid >> 5;
    const int lane  = tid & 31;
    const int wm    = (warp >> 1) << 6;
    const int wn    = (warp & 1) << 6;
    const int lane7 = lane & 7;
    const int sel   = lane >> 3;
    const int grp   = lane >> 2;
    const int qt    = lane & 3;

    const int mb = blockIdx.y * 128;
    const int nb = blockIdx.x * 128;
    const int NT = K / BK;

    float acc[4][8][4];
    #pragma unroll
    for (int i = 0; i < 4; ++i)
        #pragma unroll
        for (int j = 0; j < 8; ++j)
            #pragma unroll
            for (int q = 0; q < 4; ++q)
                acc[i][j][q] = 0.f;

    load_stage(sb + 0 * STG_BYTES, A, W, mb, nb, K, 0, tid);
    load_stage(sb + 1 * STG_BYTES, A, W, mb, nb, K, 1, tid);

    uint32_t rA[4], rAx[4], rB[4], rBx[4];
    #pragma unroll
    for (int i = 0; i < 4; ++i) {
        uint32_t r = (uint32_t)(wm + i * 16 + ((sel & 1) << 3) + lane7);
        rA[i]  = r << 7;
        rAx[i] = r & 7;
    }
    #pragma unroll
    for (int j = 0; j < 4; ++j) {
        uint32_t r = (uint32_t)(wn + j * 16 + ((sel >> 1) << 3) + lane7);
        rB[j]  = r << 7;
        rBx[j] = r & 7;
    }
    const uint32_t cA0 = (uint32_t)(sel >> 1);
    const uint32_t cB0 = (uint32_t)(sel & 1);

    for (int kt = 0; kt < NT; ++kt) {
        cp_wait(kt < NT - 1 ? 1 : 0);
        __syncthreads();

        const uint32_t aS = sb + (uint32_t)(kt % NSTG) * STG_BYTES;
        const uint32_t bS = aS + 16384;

        #pragma unroll
        for (int ks = 0; ks < 4; ++ks) {
            uint32_t af[4][4], bf[8][2];
            #pragma unroll
            for (int i = 0; i < 4; ++i) {
                uint32_t c = (uint32_t)(2 * ks) + cA0;
                ldm4(af[i], aS + rA[i] + ((c ^ rAx[i]) << 4));
            }
            #pragma unroll
            for (int j = 0; j < 4; ++j) {
                uint32_t c = (uint32_t)(2 * ks) + cB0;
                uint32_t r4[4];
                ldm4(r4, bS + rB[j] + ((c ^ rBx[j]) << 4));
                bf[2 * j][0]     = r4[0];
                bf[2 * j][1]     = r4[1];
                bf[2 * j + 1][0] = r4[2];
                bf[2 * j + 1][1] = r4[3];
            }

            if (ks == 0 && kt + 2 < NT)
                load_stage(sb + (uint32_t)((kt + 2) % NSTG) * STG_BYTES, A, W, mb, nb, K, kt + 2, tid);

            #pragma unroll
            for (int i = 0; i < 4; ++i)
                #pragma unroll
                for (int j = 0; j < 8; ++j)
                    mma_fp16(acc[i][j], af[i], bf[j]);
        }
    }

    #pragma unroll
    for (int i = 0; i < 4; ++i) {
        const int r0 = mb + wm + i * 16 + grp;
        #pragma unroll
        for (int j = 0; j < 8; ++j) {
            const int cc = nb + wn + j * 8 + (qt << 1);
            float2 bb = *(const float2*)(bias + cc);
            float v00 = acc[i][j][0] + bb.x, v01 = acc[i][j][1] + bb.y;
            float v10 = acc[i][j][2] + bb.x, v11 = acc[i][j][3] + bb.y;
            if (HALF_OUT) {
                __half* C = (__half*)Cv;
                __half2 h0 = __floats2half2_rn(v00, v01);
                __half2 h1 = __floats2half2_rn(v10, v11);
                *(uint32_t*)(C + (size_t)r0 * N + cc)       = *(uint32_t*)&h0;
                *(uint32_t*)(C + (size_t)(r0 + 8) * N + cc) = *(uint32_t*)&h1;
            } else {
                float* C = (float*)Cv;
                float2 v0{v00, v01}, v1{v10, v11};
                *(float2*)(C + (size_t)r0 * N + cc)       = v0;
                *(float2*)(C + (size_t)(r0 + 8) * N + cc) = v1;
            }
        }
    }
}

// ---------------- MMA attention: 1 warp per token, 4 tokens per block ----------------
__global__ __launch_bounds__(128, 4) void attn_mma(
    const __half* __restrict__ qkv, __half* __restrict__ out)
{
    __shared__ __align__(16) char sm[4 * 12288];
    const uint32_t sb = smem_u32(sm);
    const int tid  = threadIdx.x;
    const int w    = tid >> 5;
    const int lane = tid & 31;
    const int t0   = blockIdx.x * 4;

    #pragma unroll
    for (int i = 0; i < 24; ++i) {
        int j = tid + i * 128;
        int s = j / 768;
        int r = j - s * 768;
        int which = r >> 8;
        int hr    = (r >> 4) & 15;
        int c     = r & 15;
        uint32_t d = (uint32_t)s * 12288 + (uint32_t)which * 4096
                   + (uint32_t)hr * 256 + ((uint32_t)(c ^ (hr & 7)) << 4);
        cp16(sb + d, qkv + ((size_t)(t0 + s) * 6144 + which * 2048 + hr * 128 + c * 8));
    }
    cp_commit();
    cp_wait(0);
    __syncthreads();

    const uint32_t qb = sb + (uint32_t)w * 12288;
    const uint32_t kb = qb + 4096;
    const uint32_t vb = qb + 8192;

    const int lane7 = lane & 7;
    const int sel   = lane >> 3;
    const int grp   = lane >> 2;
    const int qt    = lane & 3;

    const uint32_t rowA  = ((uint32_t)(sel & 1) << 3) + lane7;
    const uint32_t aRow  = qb + rowA * 256;
    const uint32_t rAx   = rowA & 7;
    const uint32_t rowB  = ((uint32_t)(sel >> 1) << 3) + lane7;
    const uint32_t bRow  = kb + rowB * 256;
    const uint32_t rBx   = rowB & 7;
    const uint32_t vRowi = ((uint32_t)(sel & 1) << 3) + lane7;
    const uint32_t vRow  = vb + vRowi * 256;
    const uint32_t rVx   = vRowi & 7;

    float s0[4] = {0.f, 0.f, 0.f, 0.f};
    float s1[4] = {0.f, 0.f, 0.f, 0.f};
    #pragma unroll
    for (int kk = 0; kk < 8; ++kk) {
        uint32_t a[4], k4[4];
        uint32_t cA = (uint32_t)(kk * 2) + (uint32_t)(sel >> 1);
        ldm4(a, aRow + ((cA ^ rAx) << 4));
        uint32_t cB = (uint32_t)(kk * 2) + (uint32_t)(sel & 1);
        ldm4(k4, bRow + ((cB ^ rBx) << 4));
        mma_fp16(s0, a, k4);
        mma_fp16(s1, a, k4 + 2);
    }

    const float sc = 0.022097086912079608f;   // 1/sqrt(2048)
    float l0 = s0[0]*sc, l1 = s0[1]*sc, l2 = s1[0]*sc, l3 = s1[1]*sc;
    float h0 = s0[2]*sc, h1 = s0[3]*sc, h2 = s1[2]*sc, h3 = s1[3]*sc;

    float mlo = fmaxf(fmaxf(l0, l1), fmaxf(l2, l3));
    float mhi = fmaxf(fmaxf(h0, h1), fmaxf(h2, h3));
    #pragma unroll
    for (int o = 1; o <= 2; o <<= 1) {
        mlo = fmaxf(mlo, __shfl_xor_sync(0xFFFFFFFFu, mlo, o));
        mhi = fmaxf(mhi, __shfl_xor_sync(0xFFFFFFFFu, mhi, o));
    }
    float e0 = __expf(l0 - mlo), e1 = __expf(l1 - mlo), e2 = __expf(l2 - mlo), e3 = __expf(l3 - mlo);
    float f0 = __expf(h0 - mhi), f1 = __expf(h1 - mhi), f2 = __expf(h2 - mhi), f3 = __expf(h3 - mhi);
    float slo = e0 + e1 + e2 + e3;
    float shi = f0 + f1 + f2 + f3;
    #pragma unroll
    for (int o = 1; o <= 2; o <<= 1) {
        slo += __shfl_xor_sync(0xFFFFFFFFu, slo, o);
        shi += __shfl_xor_sync(0xFFFFFFFFu, shi, o);
    }
    const float ilo = 1.f / slo, ihi = 1.f / shi;

    uint32_t pa[4];
    {
        __half2 t;
        t = __floats2half2_rn(e0 * ilo, e1 * ilo); pa[0] = *(uint32_t*)&t;
        t = __floats2half2_rn(f0 * ihi, f1 * ihi); pa[1] = *(uint32_t*)&t;
        t = __floats2half2_rn(e2 * ilo, e3 * ilo); pa[2] = *(uint32_t*)&t;
        t = __floats2half2_rn(f2 * ihi, f3 * ihi); pa[3] = *(uint32_t*)&t;
    }

    float o[16][4];
    #pragma unroll
    for (int i = 0; i < 16; ++i)
        #pragma unroll
        for (int q = 0; q < 4; ++q)
            o[i][q] = 0.f;

    #pragma unroll
    for (int dt = 0; dt < 8; ++dt) {
        uint32_t cV = (uint32_t)(dt * 2) + (uint32_t)(sel >> 1);
        uint32_t v4[4];
        ldm4t(v4, vRow + ((cV ^ rVx) << 4));
        mma_fp16(o[2 * dt],     pa, v4);
        mma_fp16(o[2 * dt + 1], pa, v4 + 2);
    }

    const int t = t0 + w;
    const int b = t >> 11;
    const int n = t & 2047;
    const size_t blk = (size_t)b * 4194304u + (size_t)(n >> 4) * 2048 + (size_t)(n & 15) * 128;
    const size_t ob_lo = blk + (size_t)grp * (128u * 2048u);
    const size_t ob_hi = blk + (size_t)(grp + 8) * (128u * 2048u);
    #pragma unroll
    for (int dt = 0; dt < 16; ++dt) {
        const int d = dt * 8 + 2 * qt;
        __half2 vlo = __floats2half2_rn(o[dt][0], o[dt][1]);
        __half2 vhi = __floats2half2_rn(o[dt][2], o[dt][3]);
        *(uint32_t*)(out + ob_lo + d) = *(uint32_t*)&vlo;
        *(uint32_t*)(out + ob_hi + d) = *(uint32_t*)&vhi;
    }
}

extern "C" void kernel_launch(void* const* d_in, const int* in_sizes, int n_in,
                              void* d_out, int out_size)
{
    const float* x     = (const float*)d_in[0];
    const float* w_qkv = (const float*)d_in[1];
    const float* b_qkv = (const float*)d_in[2];
    const float* w_out = (const float*)d_in[3];
    const float* b_out = (const float*)d_in[4];
    float* out = (float*)d_out;

    __half *qkv, *hx, *hw1, *hw2, *att;
    cudaGetSymbolAddress((void**)&qkv, g_qkv);
    cudaGetSymbolAddress((void**)&hx,  g_hx);
    cudaGetSymbolAddress((void**)&hw1, g_hw1);
    cudaGetSymbolAddress((void**)&hw2, g_hw2);
    cudaGetSymbolAddress((void**)&att, g_att);

    // one conversion launch: 8388608 float4 total / 512 per block
    f2h_all<<<16384, 256>>>((const float4*)x, (const float4*)w_qkv, (const float4*)w_out,
                            (uint2*)hx, (uint2*)hw1, (uint2*)hw2);

    const int smem_bytes = NSTG * STG_BYTES;   // 96KB
    cudaFuncSetAttribute(gemm_fp16<true>,  cudaFuncAttributeMaxDynamicSharedMemorySize, smem_bytes);
    cudaFuncSetAttribute(gemm_fp16<false>, cudaFuncAttributeMaxDynamicSharedMemorySize, smem_bytes);

    // QKV projection -> fp16 qkv
    dim3 g1(6144 / 128, 8192 / 128);
    gemm_fp16<true><<<g1, 128, smem_bytes>>>(hx, hw1, b_qkv, qkv, 8192, 6144, 2048);

    // MMA attention + permutation (fp16 -> fp16), 4 tokens/block
    attn_mma<<<2048, 128>>>(qkv, att);

    // output projection -> fp32 out
    dim3 g2(2048 / 128, 8192 / 128);
    gemm_fp16<false><<<g2, 128, smem_bytes>>>(att, hw2, b_out, out, 8192, 2048, 2048);
}